// round 1
// baseline (speedup 1.0000x reference)
#include <cuda_runtime.h>

// Problem shape (fixed)
#define BSZ   8
#define SSZ   512
#define HDIM  4096
#define NH    64
#define HD    64
#define MDIM  (BSZ*SSZ)      // 4096 rows
#define NHEADS (BSZ*NH)      // 512

// ---------------- scratch (device globals; no allocations allowed) ----------------
__device__ float g_q[(size_t)MDIM*HDIM];
__device__ float g_k[(size_t)MDIM*HDIM];
__device__ float g_v[(size_t)MDIM*HDIM];
__device__ float g_ctx[(size_t)MDIM*HDIM];
__device__ float g_proj[(size_t)MDIM*HDIM];
__device__ float g_sp[(size_t)NHEADS*SSZ*SSZ];   // scores, then probs (in-place)
__device__ float g_maxes[8];
// max indices: 0=q 1=k 2=v 3=scores 4=probs 5=ctx 6=proj 7=final

// ---------------- helpers ----------------
__device__ __forceinline__ float scale_from_max(float m) {
    m = fmaxf(m, 1e-12f);
    // scale = 2^(16 - (ceil(log2 m)+1)) = 2^(15 - ceil(log2 m))  (exact power of two)
    return exp2f(15.0f - ceilf(log2f(m)));
}
__device__ __forceinline__ float quantv(float x, float s, float inv) {
    float r = rintf(x * s);                      // round half-to-even, matches jnp.round
    r = fminf(fmaxf(r, -32768.0f), 32767.0f);
    return r * inv;                              // inv = 1/s exact (power of two)
}
__device__ __forceinline__ void atomic_amax(float* a, float v) {
    atomicMax((int*)a, __float_as_int(v));       // valid for non-negative floats
}
__device__ __forceinline__ float block_reduce_max(float v, float* sm) {
    int t = threadIdx.x;
    sm[t] = v; __syncthreads();
    for (int off = blockDim.x >> 1; off > 0; off >>= 1) {
        if (t < off) sm[t] = fmaxf(sm[t], sm[t + off]);
        __syncthreads();
    }
    float r = sm[0]; __syncthreads();
    return r;
}
__device__ __forceinline__ float block_reduce_sum(float v, float* sm) {
    int t = threadIdx.x;
    sm[t] = v; __syncthreads();
    for (int off = blockDim.x >> 1; off > 0; off >>= 1) {
        if (t < off) sm[t] += sm[t + off];
        __syncthreads();
    }
    float r = sm[0]; __syncthreads();
    return r;
}

__global__ void reset_kernel() {
    if (threadIdx.x < 8) g_maxes[threadIdx.x] = 0.0f;
}

// ---------------- big GEMM:  C[m,n] = sum_k A[m,k]*W[n,k] + bias[n], abs-max epilogue ----------------
// M=N=K=4096. Block tile 128x128, BK=16, 256 threads, 8x8 per thread.
__global__ __launch_bounds__(256) void gemm_nt_kernel(
    const float* __restrict__ A, const float* __restrict__ W,
    const float* __restrict__ bias, float* __restrict__ C, int maxidx)
{
    __shared__ float As[16][128];
    __shared__ float Bs[16][128];
    __shared__ float red[256];
    const int tid = threadIdx.x;
    const int rowBase = blockIdx.y * 128;
    const int colBase = blockIdx.x * 128;
    const int tm = tid >> 4, tn = tid & 15;

    float acc[8][8];
#pragma unroll
    for (int i = 0; i < 8; i++)
#pragma unroll
        for (int j = 0; j < 8; j++) acc[i][j] = 0.0f;

    for (int k0 = 0; k0 < 4096; k0 += 16) {
#pragma unroll
        for (int it = 0; it < 2; ++it) {
            int id = tid + it * 256;       // 0..511
            int r = id >> 2;               // 0..127
            int c = (id & 3) << 2;         // 0,4,8,12
            float4 av = *(const float4*)(A + (size_t)(rowBase + r) * 4096 + k0 + c);
            As[c + 0][r] = av.x; As[c + 1][r] = av.y; As[c + 2][r] = av.z; As[c + 3][r] = av.w;
            float4 bv = *(const float4*)(W + (size_t)(colBase + r) * 4096 + k0 + c);
            Bs[c + 0][r] = bv.x; Bs[c + 1][r] = bv.y; Bs[c + 2][r] = bv.z; Bs[c + 3][r] = bv.w;
        }
        __syncthreads();
#pragma unroll
        for (int k = 0; k < 16; k++) {
            float a[8], b[8];
            *(float4*)&a[0] = *(const float4*)&As[k][tm * 8];
            *(float4*)&a[4] = *(const float4*)&As[k][tm * 8 + 4];
            *(float4*)&b[0] = *(const float4*)&Bs[k][tn * 8];
            *(float4*)&b[4] = *(const float4*)&Bs[k][tn * 8 + 4];
#pragma unroll
            for (int i = 0; i < 8; i++)
#pragma unroll
                for (int j = 0; j < 8; j++) acc[i][j] += a[i] * b[j];
        }
        __syncthreads();
    }

    float bb[8];
#pragma unroll
    for (int j = 0; j < 8; j++) bb[j] = bias[colBase + tn * 8 + j];
    float amax = 0.0f;
#pragma unroll
    for (int i = 0; i < 8; i++) {
        float* crow = C + (size_t)(rowBase + tm * 8 + i) * 4096 + colBase + tn * 8;
#pragma unroll
        for (int j = 0; j < 8; j++) {
            float v = acc[i][j] + bb[j];
            crow[j] = v;
            amax = fmaxf(amax, fabsf(v));
        }
    }
    amax = block_reduce_max(amax, red);
    if (tid == 0) atomic_amax(&g_maxes[maxidx], amax);
}

// ---------------- elementwise quantize (in place) ----------------
__global__ void quant_kernel(float* __restrict__ p, int n4, int maxidx) {
    float s = scale_from_max(g_maxes[maxidx]);
    float inv = 1.0f / s;
    int i = blockIdx.x * blockDim.x + threadIdx.x;
    if (i < n4) {
        float4 v = ((float4*)p)[i];
        v.x = quantv(v.x, s, inv);
        v.y = quantv(v.y, s, inv);
        v.z = quantv(v.z, s, inv);
        v.w = quantv(v.w, s, inv);
        ((float4*)p)[i] = v;
    }
}

// ---------------- scores = q @ k^T / 8 per head; store raw + global abs-max ----------------
// grid (8 i-tiles, 8 j-tiles, 512 heads); 64x64 tile, K=64
__global__ __launch_bounds__(256) void scores_kernel() {
    __shared__ float Qs[64][64];   // [k][i]
    __shared__ float Ks[64][64];   // [k][j]
    __shared__ float red[256];
    const int head = blockIdx.z;
    const int b = head >> 6, n = head & 63;
    const int i0 = blockIdx.x * 64, j0 = blockIdx.y * 64;
    const float* qb = g_q + (size_t)(b * 512 + i0) * 4096 + n * 64;
    const float* kb = g_k + (size_t)(b * 512 + j0) * 4096 + n * 64;
    const int tid = threadIdx.x;

#pragma unroll
    for (int it = 0; it < 4; ++it) {
        int id = tid + it * 256;          // 0..1023
        int r = id >> 4;                  // 0..63
        int c = (id & 15) << 2;           // 0..60
        float4 qv = *(const float4*)(qb + (size_t)r * 4096 + c);
        Qs[c + 0][r] = qv.x; Qs[c + 1][r] = qv.y; Qs[c + 2][r] = qv.z; Qs[c + 3][r] = qv.w;
        float4 kv = *(const float4*)(kb + (size_t)r * 4096 + c);
        Ks[c + 0][r] = kv.x; Ks[c + 1][r] = kv.y; Ks[c + 2][r] = kv.z; Ks[c + 3][r] = kv.w;
    }
    __syncthreads();

    const int tm = tid >> 4, tn = tid & 15;
    float acc[4][4];
#pragma unroll
    for (int i = 0; i < 4; i++)
#pragma unroll
        for (int j = 0; j < 4; j++) acc[i][j] = 0.0f;

#pragma unroll 16
    for (int k = 0; k < 64; k++) {
        float a[4], bv[4];
        *(float4*)a  = *(const float4*)&Qs[k][tm * 4];
        *(float4*)bv = *(const float4*)&Ks[k][tn * 4];
#pragma unroll
        for (int i = 0; i < 4; i++)
#pragma unroll
            for (int j = 0; j < 4; j++) acc[i][j] += a[i] * bv[j];
    }

    float amax = 0.0f;
    float* out = g_sp + ((size_t)head * 512 + i0 + tm * 4) * 512 + j0 + tn * 4;
#pragma unroll
    for (int i = 0; i < 4; i++)
#pragma unroll
        for (int j = 0; j < 4; j++) {
            float v = acc[i][j] * 0.125f;   // 1/sqrt(64)
            out[(size_t)i * 512 + j] = v;
            amax = fmaxf(amax, fabsf(v));
        }
    amax = block_reduce_max(amax, red);
    if (tid == 0) atomic_amax(&g_maxes[3], amax);
}

// ---------------- quantize scores + mask + softmax -> probs (in place), probs abs-max ----------------
// block = 8 warps, 1 warp per row; grid (64 rowgroups, 512 heads)
__global__ __launch_bounds__(256) void softmax_kernel(const float* __restrict__ mask) {
    __shared__ float red8[8];
    const int head = blockIdx.y;
    const int b = head >> 6;
    const int warp = threadIdx.x >> 5, lane = threadIdx.x & 31;
    const int row = blockIdx.x * 8 + warp;
    float* sp = g_sp + ((size_t)head * 512 + row) * 512;
    const float* mrow = mask + (size_t)b * 512;

    const float s3 = scale_from_max(g_maxes[3]);
    const float inv3 = 1.0f / s3;

    float vals[16];
    float mx = -1e30f;
#pragma unroll
    for (int u = 0; u < 4; u++) {
        float4 v = ((const float4*)sp)[u * 32 + lane];
        float4 m = ((const float4*)mrow)[u * 32 + lane];
        vals[u * 4 + 0] = quantv(v.x, s3, inv3) + m.x;
        vals[u * 4 + 1] = quantv(v.y, s3, inv3) + m.y;
        vals[u * 4 + 2] = quantv(v.z, s3, inv3) + m.z;
        vals[u * 4 + 3] = quantv(v.w, s3, inv3) + m.w;
#pragma unroll
        for (int c = 0; c < 4; c++) mx = fmaxf(mx, vals[u * 4 + c]);
    }
#pragma unroll
    for (int off = 16; off > 0; off >>= 1)
        mx = fmaxf(mx, __shfl_xor_sync(0xffffffffu, mx, off));

    float sum = 0.0f;
#pragma unroll
    for (int u = 0; u < 16; u++) { vals[u] = expf(vals[u] - mx); sum += vals[u]; }
#pragma unroll
    for (int off = 16; off > 0; off >>= 1)
        sum += __shfl_xor_sync(0xffffffffu, sum, off);

    const float rs = 1.0f / sum;
    float amax = 0.0f;
#pragma unroll
    for (int u = 0; u < 4; u++) {
        float4 p;
        p.x = vals[u * 4 + 0] * rs;
        p.y = vals[u * 4 + 1] * rs;
        p.z = vals[u * 4 + 2] * rs;
        p.w = vals[u * 4 + 3] * rs;
        amax = fmaxf(amax, fmaxf(fmaxf(p.x, p.y), fmaxf(p.z, p.w)));
        ((float4*)sp)[u * 32 + lane] = p;
    }
#pragma unroll
    for (int off = 16; off > 0; off >>= 1)
        amax = fmaxf(amax, __shfl_xor_sync(0xffffffffu, amax, off));
    if (lane == 0) red8[warp] = amax;
    __syncthreads();
    if (threadIdx.x == 0) {
        float m = red8[0];
#pragma unroll
        for (int w = 1; w < 8; w++) m = fmaxf(m, red8[w]);
        atomic_amax(&g_maxes[4], m);
    }
}

// ---------------- ctx = quant(probs) @ v per head; abs-max epilogue ----------------
// grid (8 i-tiles, 512 heads); block 256; tile 64(i) x 64(d), stream j in chunks of 64
__global__ __launch_bounds__(256) void ctx_kernel() {
    __shared__ float Ps[64][64];   // [j][i]
    __shared__ float Vs[64][64];   // [j][d]
    __shared__ float red[256];
    const int head = blockIdx.y;
    const int b = head >> 6, n = head & 63;
    const int i0 = blockIdx.x * 64;
    const int tid = threadIdx.x;
    const int tm = tid >> 4, tn = tid & 15;

    const float s4 = scale_from_max(g_maxes[4]);
    const float inv4 = 1.0f / s4;

    float acc[4][4];
#pragma unroll
    for (int i = 0; i < 4; i++)
#pragma unroll
        for (int j = 0; j < 4; j++) acc[i][j] = 0.0f;

    for (int j0 = 0; j0 < 512; j0 += 64) {
#pragma unroll
        for (int it = 0; it < 4; ++it) {
            int id = tid + it * 256;
            int r = id >> 4;
            int c = (id & 15) << 2;
            float4 pv = *(const float4*)(g_sp + ((size_t)head * 512 + i0 + r) * 512 + j0 + c);
            Ps[c + 0][r] = quantv(pv.x, s4, inv4);
            Ps[c + 1][r] = quantv(pv.y, s4, inv4);
            Ps[c + 2][r] = quantv(pv.z, s4, inv4);
            Ps[c + 3][r] = quantv(pv.w, s4, inv4);
            float4 vv = *(const float4*)(g_v + (size_t)(b * 512 + j0 + r) * 4096 + n * 64 + c);
            *(float4*)&Vs[r][c] = vv;
        }
        __syncthreads();
#pragma unroll 16
        for (int j = 0; j < 64; j++) {
            float a[4], bv[4];
            *(float4*)a  = *(const float4*)&Ps[j][tm * 4];
            *(float4*)bv = *(const float4*)&Vs[j][tn * 4];
#pragma unroll
            for (int i = 0; i < 4; i++)
#pragma unroll
                for (int jj = 0; jj < 4; jj++) acc[i][jj] += a[i] * bv[jj];
        }
        __syncthreads();
    }

    float amax = 0.0f;
#pragma unroll
    for (int i = 0; i < 4; i++) {
        float* crow = g_ctx + (size_t)(b * 512 + i0 + tm * 4 + i) * 4096 + n * 64 + tn * 4;
#pragma unroll
        for (int j = 0; j < 4; j++) {
            float v = acc[i][j];
            crow[j] = v;
            amax = fmaxf(amax, fabsf(v));
        }
    }
    amax = block_reduce_max(amax, red);
    if (tid == 0) atomic_amax(&g_maxes[5], amax);
}

// ---------------- quant(proj) + residual + LayerNorm, abs-max of output ----------------
__global__ __launch_bounds__(256) void ln_kernel(
    const float* __restrict__ x, const float* __restrict__ lnw,
    const float* __restrict__ lnb, float* __restrict__ out)
{
    __shared__ float ybuf[4096];
    __shared__ float red[256];
    const int r = blockIdx.x;
    const int tid = threadIdx.x;
    const float s6 = scale_from_max(g_maxes[6]);
    const float inv6 = 1.0f / s6;
    const float* xr = x + (size_t)r * 4096;
    const float* pr = g_proj + (size_t)r * 4096;

    float sum = 0.0f;
    for (int i = tid; i < 4096; i += 256) {
        float y = xr[i] + quantv(pr[i], s6, inv6);
        ybuf[i] = y;
        sum += y;
    }
    sum = block_reduce_sum(sum, red);
    const float mu = sum * (1.0f / 4096.0f);

    float s2 = 0.0f;
    for (int i = tid; i < 4096; i += 256) {
        float d = ybuf[i] - mu;
        s2 += d * d;
    }
    s2 = block_reduce_sum(s2, red);
    const float var = s2 * (1.0f / 4096.0f);
    const float rinv = rsqrtf(var + 1e-12f);

    float amax = 0.0f;
    float* orow = out + (size_t)r * 4096;
    for (int i = tid; i < 4096; i += 256) {
        float o = (ybuf[i] - mu) * rinv * lnw[i] + lnb[i];
        orow[i] = o;
        amax = fmaxf(amax, fabsf(o));
    }
    amax = block_reduce_max(amax, red);
    if (tid == 0) atomic_amax(&g_maxes[7], amax);
}

// ---------------- launch ----------------
static float* sym_addr(const void* sym) {
    void* p = nullptr;
    cudaGetSymbolAddress(&p, sym);
    return (float*)p;
}

extern "C" void kernel_launch(void* const* d_in, const int* in_sizes, int n_in,
                              void* d_out, int out_size)
{
    (void)in_sizes; (void)n_in; (void)out_size;
    const float* x    = (const float*)d_in[0];
    const float* mask = (const float*)d_in[1];
    const float* Wq   = (const float*)d_in[2];
    const float* bq   = (const float*)d_in[3];
    const float* Wk   = (const float*)d_in[4];
    const float* bk   = (const float*)d_in[5];
    const float* Wv   = (const float*)d_in[6];
    const float* bv   = (const float*)d_in[7];
    const float* Wd   = (const float*)d_in[8];
    const float* bd   = (const float*)d_in[9];
    const float* lnw  = (const float*)d_in[10];
    const float* lnb  = (const float*)d_in[11];
    float* out = (float*)d_out;

    float* q    = sym_addr(g_q);
    float* k    = sym_addr(g_k);
    float* v    = sym_addr(g_v);
    float* ctx  = sym_addr(g_ctx);
    float* proj = sym_addr(g_proj);

    const int n4 = (MDIM * HDIM) / 4;           // 4,194,304
    const int qblocks = n4 / 256;               // 16384

    reset_kernel<<<1, 32>>>();

    dim3 gg(32, 32);
    gemm_nt_kernel<<<gg, 256>>>(x, Wq, bq, q, 0);
    gemm_nt_kernel<<<gg, 256>>>(x, Wk, bk, k, 1);
    gemm_nt_kernel<<<gg, 256>>>(x, Wv, bv, v, 2);

    quant_kernel<<<qblocks, 256>>>(q, n4, 0);
    quant_kernel<<<qblocks, 256>>>(k, n4, 1);
    quant_kernel<<<qblocks, 256>>>(v, n4, 2);

    scores_kernel<<<dim3(8, 8, 512), 256>>>();
    softmax_kernel<<<dim3(64, 512), 256>>>(mask);
    ctx_kernel<<<dim3(8, 512), 256>>>();

    quant_kernel<<<qblocks, 256>>>(ctx, n4, 5);

    gemm_nt_kernel<<<gg, 256>>>(ctx, Wd, bd, proj, 6);

    ln_kernel<<<MDIM, 256>>>(x, lnw, lnb, out);
    quant_kernel<<<qblocks, 256>>>(out, n4, 7);
}

// round 3
// speedup vs baseline: 2.5992x; 2.5992x over previous
#include <cuda_runtime.h>

// Problem shape (fixed)
#define BSZ   8
#define SSZ   512
#define HDIM  4096
#define NH    64
#define HD    64
#define MDIM  (BSZ*SSZ)      // 4096 rows
#define NHEADS (BSZ*NH)      // 512

// ---------------- scratch (device globals; no allocations allowed) ----------------
__device__ float g_q[(size_t)MDIM*HDIM];
__device__ float g_k[(size_t)MDIM*HDIM];
__device__ float g_v[(size_t)MDIM*HDIM];
__device__ float g_ctx[(size_t)MDIM*HDIM];
__device__ float g_proj[(size_t)MDIM*HDIM];
__device__ float g_sp[(size_t)NHEADS*SSZ*SSZ];   // scores, then probs (in-place)
__device__ float g_maxes[8];
// max indices: 0=q 1=k 2=v 3=scores 4=probs 5=ctx 6=proj 7=final

// ---------------- helpers ----------------
__device__ __forceinline__ float scale_from_max(float m) {
    m = fmaxf(m, 1e-12f);
    return exp2f(15.0f - ceilf(log2f(m)));   // exact power of two
}
__device__ __forceinline__ float quantv(float x, float s, float inv) {
    float r = rintf(x * s);
    r = fminf(fmaxf(r, -32768.0f), 32767.0f);
    return r * inv;
}
__device__ __forceinline__ void atomic_amax(float* a, float v) {
    atomicMax((int*)a, __float_as_int(v));   // valid for non-negative floats
}
__device__ __forceinline__ float block_reduce_max(float v, float* sm) {
    int t = threadIdx.x;
    sm[t] = v; __syncthreads();
    for (int off = blockDim.x >> 1; off > 0; off >>= 1) {
        if (t < off) sm[t] = fmaxf(sm[t], sm[t + off]);
        __syncthreads();
    }
    float r = sm[0]; __syncthreads();
    return r;
}
__device__ __forceinline__ float block_reduce_sum(float v, float* sm) {
    int t = threadIdx.x;
    sm[t] = v; __syncthreads();
    for (int off = blockDim.x >> 1; off > 0; off >>= 1) {
        if (t < off) sm[t] += sm[t + off];
        __syncthreads();
    }
    float r = sm[0]; __syncthreads();
    return r;
}
__device__ __forceinline__ unsigned f2tf32(float x) {
    unsigned r;
    asm("cvt.rna.tf32.f32 %0, %1;" : "=r"(r) : "f"(x));
    return r;
}
__device__ __forceinline__ void mma_tf32(
    float& c0, float& c1, float& c2, float& c3,
    unsigned a0, unsigned a1, unsigned a2, unsigned a3,
    unsigned b0, unsigned b1)
{
    asm volatile(
        "mma.sync.aligned.m16n8k8.row.col.f32.tf32.tf32.f32 "
        "{%0,%1,%2,%3}, {%4,%5,%6,%7}, {%8,%9}, {%0,%1,%2,%3};"
        : "+f"(c0), "+f"(c1), "+f"(c2), "+f"(c3)
        : "r"(a0), "r"(a1), "r"(a2), "r"(a3), "r"(b0), "r"(b1));
}
__device__ __forceinline__ void cp_async16(unsigned smem_addr, const void* gptr) {
    asm volatile("cp.async.cg.shared.global [%0], [%1], 16;" :: "r"(smem_addr), "l"(gptr));
}
__device__ __forceinline__ void cp_commit() {
    asm volatile("cp.async.commit_group;" ::: "memory");
}
template<int N> __device__ __forceinline__ void cp_wait() {
    asm volatile("cp.async.wait_group %0;" :: "n"(N) : "memory");
}

__global__ void reset_kernel() {
    if (threadIdx.x < 8) g_maxes[threadIdx.x] = 0.0f;
}

// ---------------- tf32 tensor-core GEMM: C[m,n] = sum_k A[m,k]*W[n,k] + bias[n] ----------------
// M=N=K=4096. Block 128x128, BK=16, 256 threads (8 warps), warp tile 64x32.
#define BKT 16
#define KSTRIDE 20   // BKT + 4 pad: conflict-free frag LDS, 16B-aligned rows for cp.async

__global__ __launch_bounds__(256) void gemm_tf32_kernel(
    const float* __restrict__ A, const float* __restrict__ W,
    const float* __restrict__ bias, float* __restrict__ C, int maxidx)
{
    __shared__ float As[2][128][KSTRIDE];
    __shared__ float Bs[2][128][KSTRIDE];
    __shared__ float red[256];

    const int tid   = threadIdx.x;
    const int wid   = tid >> 5;
    const int lane  = tid & 31;
    const int g     = lane >> 2;     // groupID
    const int tg    = lane & 3;      // thread-in-group
    const int warp_m = wid & 1;      // 2 warps along M (64 each)
    const int warp_n = wid >> 1;     // 4 warps along N (32 each)
    const int rowBase = blockIdx.y * 128;
    const int colBase = blockIdx.x * 128;

    // cp.async copy mapping: 512 chunks of 16B per matrix tile; 2 chunks/thread
    const int c_row0 = tid >> 2;            // chunk tid  : rows 0..63
    const int c_seg  = (tid & 3) << 2;      // float offset within 16-float row
    const int c_row1 = c_row0 + 64;         // chunk tid+256

    float acc[4][4][4];
#pragma unroll
    for (int mt = 0; mt < 4; mt++)
#pragma unroll
        for (int nt = 0; nt < 4; nt++)
#pragma unroll
            for (int i = 0; i < 4; i++) acc[mt][nt][i] = 0.0f;

    auto issue_copy = [&](int buf, int k0) {
        const float* asrc0 = A + (size_t)(rowBase + c_row0) * 4096 + k0 + c_seg;
        const float* asrc1 = A + (size_t)(rowBase + c_row1) * 4096 + k0 + c_seg;
        const float* bsrc0 = W + (size_t)(colBase + c_row0) * 4096 + k0 + c_seg;
        const float* bsrc1 = W + (size_t)(colBase + c_row1) * 4096 + k0 + c_seg;
        cp_async16((unsigned)__cvta_generic_to_shared(&As[buf][c_row0][c_seg]), asrc0);
        cp_async16((unsigned)__cvta_generic_to_shared(&As[buf][c_row1][c_seg]), asrc1);
        cp_async16((unsigned)__cvta_generic_to_shared(&Bs[buf][c_row0][c_seg]), bsrc0);
        cp_async16((unsigned)__cvta_generic_to_shared(&Bs[buf][c_row1][c_seg]), bsrc1);
        cp_commit();
    };

    issue_copy(0, 0);

    const int NITER = 4096 / BKT;   // 256
    for (int iter = 0; iter < NITER; iter++) {
        const int buf = iter & 1;
        if (iter + 1 < NITER) {
            issue_copy(buf ^ 1, (iter + 1) * BKT);
            cp_wait<1>();
        } else {
            cp_wait<0>();
        }
        __syncthreads();

#pragma unroll
        for (int ks = 0; ks < 2; ks++) {
            const int kb = ks * 8;
            unsigned af[4][4];
#pragma unroll
            for (int mt = 0; mt < 4; mt++) {
                const int m = warp_m * 64 + mt * 16 + g;
                af[mt][0] = f2tf32(As[buf][m    ][kb + tg]);
                af[mt][1] = f2tf32(As[buf][m + 8][kb + tg]);
                af[mt][2] = f2tf32(As[buf][m    ][kb + tg + 4]);
                af[mt][3] = f2tf32(As[buf][m + 8][kb + tg + 4]);
            }
            unsigned bf[4][2];
#pragma unroll
            for (int nt = 0; nt < 4; nt++) {
                const int n = warp_n * 32 + nt * 8 + g;
                bf[nt][0] = f2tf32(Bs[buf][n][kb + tg]);
                bf[nt][1] = f2tf32(Bs[buf][n][kb + tg + 4]);
            }
#pragma unroll
            for (int mt = 0; mt < 4; mt++)
#pragma unroll
                for (int nt = 0; nt < 4; nt++)
                    mma_tf32(acc[mt][nt][0], acc[mt][nt][1], acc[mt][nt][2], acc[mt][nt][3],
                             af[mt][0], af[mt][1], af[mt][2], af[mt][3],
                             bf[nt][0], bf[nt][1]);
        }
        __syncthreads();
    }

    // epilogue: bias, store, abs-max
    float amax = 0.0f;
#pragma unroll
    for (int mt = 0; mt < 4; mt++) {
        const int row0 = rowBase + warp_m * 64 + mt * 16 + g;
#pragma unroll
        for (int nt = 0; nt < 4; nt++) {
            const int col = colBase + warp_n * 32 + nt * 8 + tg * 2;
            const float b0 = bias[col], b1 = bias[col + 1];
            float v0 = acc[mt][nt][0] + b0;
            float v1 = acc[mt][nt][1] + b1;
            float v2 = acc[mt][nt][2] + b0;
            float v3 = acc[mt][nt][3] + b1;
            *(float2*)(C + (size_t)row0 * 4096 + col)       = make_float2(v0, v1);
            *(float2*)(C + (size_t)(row0 + 8) * 4096 + col) = make_float2(v2, v3);
            amax = fmaxf(amax, fmaxf(fmaxf(fabsf(v0), fabsf(v1)), fmaxf(fabsf(v2), fabsf(v3))));
        }
    }
    amax = block_reduce_max(amax, red);
    if (tid == 0) atomic_amax(&g_maxes[maxidx], amax);
}

// ---------------- elementwise quantize (in place) ----------------
__global__ void quant_kernel(float* __restrict__ p, int n4, int maxidx) {
    float s = scale_from_max(g_maxes[maxidx]);
    float inv = 1.0f / s;
    int i = blockIdx.x * blockDim.x + threadIdx.x;
    if (i < n4) {
        float4 v = ((float4*)p)[i];
        v.x = quantv(v.x, s, inv);
        v.y = quantv(v.y, s, inv);
        v.z = quantv(v.z, s, inv);
        v.w = quantv(v.w, s, inv);
        ((float4*)p)[i] = v;
    }
}

// ---------------- scores = q @ k^T / 8 per head; store raw + global abs-max ----------------
__global__ __launch_bounds__(256) void scores_kernel() {
    __shared__ float Qs[64][64];   // [k][i]
    __shared__ float Ks[64][64];   // [k][j]
    __shared__ float red[256];
    const int head = blockIdx.z;
    const int b = head >> 6, n = head & 63;
    const int i0 = blockIdx.x * 64, j0 = blockIdx.y * 64;
    const float* qb = g_q + (size_t)(b * 512 + i0) * 4096 + n * 64;
    const float* kb = g_k + (size_t)(b * 512 + j0) * 4096 + n * 64;
    const int tid = threadIdx.x;

#pragma unroll
    for (int it = 0; it < 4; ++it) {
        int id = tid + it * 256;
        int r = id >> 4;
        int c = (id & 15) << 2;
        float4 qv = *(const float4*)(qb + (size_t)r * 4096 + c);
        Qs[c + 0][r] = qv.x; Qs[c + 1][r] = qv.y; Qs[c + 2][r] = qv.z; Qs[c + 3][r] = qv.w;
        float4 kv = *(const float4*)(kb + (size_t)r * 4096 + c);
        Ks[c + 0][r] = kv.x; Ks[c + 1][r] = kv.y; Ks[c + 2][r] = kv.z; Ks[c + 3][r] = kv.w;
    }
    __syncthreads();

    const int tm = tid >> 4, tn = tid & 15;
    float acc[4][4];
#pragma unroll
    for (int i = 0; i < 4; i++)
#pragma unroll
        for (int j = 0; j < 4; j++) acc[i][j] = 0.0f;

#pragma unroll 16
    for (int k = 0; k < 64; k++) {
        float a[4], bv[4];
        *(float4*)a  = *(const float4*)&Qs[k][tm * 4];
        *(float4*)bv = *(const float4*)&Ks[k][tn * 4];
#pragma unroll
        for (int i = 0; i < 4; i++)
#pragma unroll
            for (int j = 0; j < 4; j++) acc[i][j] += a[i] * bv[j];
    }

    float amax = 0.0f;
    float* out = g_sp + ((size_t)head * 512 + i0 + tm * 4) * 512 + j0 + tn * 4;
#pragma unroll
    for (int i = 0; i < 4; i++)
#pragma unroll
        for (int j = 0; j < 4; j++) {
            float v = acc[i][j] * 0.125f;
            out[(size_t)i * 512 + j] = v;
            amax = fmaxf(amax, fabsf(v));
        }
    amax = block_reduce_max(amax, red);
    if (tid == 0) atomic_amax(&g_maxes[3], amax);
}

// ---------------- quantize scores + mask + softmax -> probs (in place), probs abs-max ----------------
__global__ __launch_bounds__(256) void softmax_kernel(const float* __restrict__ mask) {
    __shared__ float red8[8];
    const int head = blockIdx.y;
    const int b = head >> 6;
    const int warp = threadIdx.x >> 5, lane = threadIdx.x & 31;
    const int row = blockIdx.x * 8 + warp;
    float* sp = g_sp + ((size_t)head * 512 + row) * 512;
    const float* mrow = mask + (size_t)b * 512;

    const float s3 = scale_from_max(g_maxes[3]);
    const float inv3 = 1.0f / s3;

    float vals[16];
    float mx = -1e30f;
#pragma unroll
    for (int u = 0; u < 4; u++) {
        float4 v = ((const float4*)sp)[u * 32 + lane];
        float4 m = ((const float4*)mrow)[u * 32 + lane];
        vals[u * 4 + 0] = quantv(v.x, s3, inv3) + m.x;
        vals[u * 4 + 1] = quantv(v.y, s3, inv3) + m.y;
        vals[u * 4 + 2] = quantv(v.z, s3, inv3) + m.z;
        vals[u * 4 + 3] = quantv(v.w, s3, inv3) + m.w;
#pragma unroll
        for (int c = 0; c < 4; c++) mx = fmaxf(mx, vals[u * 4 + c]);
    }
#pragma unroll
    for (int off = 16; off > 0; off >>= 1)
        mx = fmaxf(mx, __shfl_xor_sync(0xffffffffu, mx, off));

    float sum = 0.0f;
#pragma unroll
    for (int u = 0; u < 16; u++) { vals[u] = expf(vals[u] - mx); sum += vals[u]; }
#pragma unroll
    for (int off = 16; off > 0; off >>= 1)
        sum += __shfl_xor_sync(0xffffffffu, sum, off);

    const float rs = 1.0f / sum;
    float amax = 0.0f;
#pragma unroll
    for (int u = 0; u < 4; u++) {
        float4 p;
        p.x = vals[u * 4 + 0] * rs;
        p.y = vals[u * 4 + 1] * rs;
        p.z = vals[u * 4 + 2] * rs;
        p.w = vals[u * 4 + 3] * rs;
        amax = fmaxf(amax, fmaxf(fmaxf(p.x, p.y), fmaxf(p.z, p.w)));
        ((float4*)sp)[u * 32 + lane] = p;
    }
#pragma unroll
    for (int off = 16; off > 0; off >>= 1)
        amax = fmaxf(amax, __shfl_xor_sync(0xffffffffu, amax, off));
    if (lane == 0) red8[warp] = amax;
    __syncthreads();
    if (threadIdx.x == 0) {
        float m = red8[0];
#pragma unroll
        for (int w = 1; w < 8; w++) m = fmaxf(m, red8[w]);
        atomic_amax(&g_maxes[4], m);
    }
}

// ---------------- ctx = quant(probs) @ v per head; abs-max epilogue ----------------
__global__ __launch_bounds__(256) void ctx_kernel() {
    __shared__ float Ps[64][64];   // [j][i]
    __shared__ float Vs[64][64];   // [j][d]
    __shared__ float red[256];
    const int head = blockIdx.y;
    const int b = head >> 6, n = head & 63;
    const int i0 = blockIdx.x * 64;
    const int tid = threadIdx.x;
    const int tm = tid >> 4, tn = tid & 15;

    const float s4 = scale_from_max(g_maxes[4]);
    const float inv4 = 1.0f / s4;

    float acc[4][4];
#pragma unroll
    for (int i = 0; i < 4; i++)
#pragma unroll
        for (int j = 0; j < 4; j++) acc[i][j] = 0.0f;

    for (int j0 = 0; j0 < 512; j0 += 64) {
#pragma unroll
        for (int it = 0; it < 4; ++it) {
            int id = tid + it * 256;
            int r = id >> 4;
            int c = (id & 15) << 2;
            float4 pv = *(const float4*)(g_sp + ((size_t)head * 512 + i0 + r) * 512 + j0 + c);
            Ps[c + 0][r] = quantv(pv.x, s4, inv4);
            Ps[c + 1][r] = quantv(pv.y, s4, inv4);
            Ps[c + 2][r] = quantv(pv.z, s4, inv4);
            Ps[c + 3][r] = quantv(pv.w, s4, inv4);
            float4 vv = *(const float4*)(g_v + (size_t)(b * 512 + j0 + r) * 4096 + n * 64 + c);
            *(float4*)&Vs[r][c] = vv;
        }
        __syncthreads();
#pragma unroll 16
        for (int j = 0; j < 64; j++) {
            float a[4], bv[4];
            *(float4*)a  = *(const float4*)&Ps[j][tm * 4];
            *(float4*)bv = *(const float4*)&Vs[j][tn * 4];
#pragma unroll
            for (int i = 0; i < 4; i++)
#pragma unroll
                for (int jj = 0; jj < 4; jj++) acc[i][jj] += a[i] * bv[jj];
        }
        __syncthreads();
    }

    float amax = 0.0f;
#pragma unroll
    for (int i = 0; i < 4; i++) {
        float* crow = g_ctx + (size_t)(b * 512 + i0 + tm * 4 + i) * 4096 + n * 64 + tn * 4;
#pragma unroll
        for (int j = 0; j < 4; j++) {
            float v = acc[i][j];
            crow[j] = v;
            amax = fmaxf(amax, fabsf(v));
        }
    }
    amax = block_reduce_max(amax, red);
    if (tid == 0) atomic_amax(&g_maxes[5], amax);
}

// ---------------- quant(proj) + residual + LayerNorm, abs-max of output ----------------
__global__ __launch_bounds__(256) void ln_kernel(
    const float* __restrict__ x, const float* __restrict__ lnw,
    const float* __restrict__ lnb, float* __restrict__ out)
{
    __shared__ float ybuf[4096];
    __shared__ float red[256];
    const int r = blockIdx.x;
    const int tid = threadIdx.x;
    const float s6 = scale_from_max(g_maxes[6]);
    const float inv6 = 1.0f / s6;
    const float* xr = x + (size_t)r * 4096;
    const float* pr = g_proj + (size_t)r * 4096;

    float sum = 0.0f;
    for (int i = tid; i < 4096; i += 256) {
        float y = xr[i] + quantv(pr[i], s6, inv6);
        ybuf[i] = y;
        sum += y;
    }
    sum = block_reduce_sum(sum, red);
    const float mu = sum * (1.0f / 4096.0f);

    float s2 = 0.0f;
    for (int i = tid; i < 4096; i += 256) {
        float d = ybuf[i] - mu;
        s2 += d * d;
    }
    s2 = block_reduce_sum(s2, red);
    const float var = s2 * (1.0f / 4096.0f);
    const float rinv = rsqrtf(var + 1e-12f);

    float amax = 0.0f;
    float* orow = out + (size_t)r * 4096;
    for (int i = tid; i < 4096; i += 256) {
        float o = (ybuf[i] - mu) * rinv * lnw[i] + lnb[i];
        orow[i] = o;
        amax = fmaxf(amax, fabsf(o));
    }
    amax = block_reduce_max(amax, red);
    if (tid == 0) atomic_amax(&g_maxes[7], amax);
}

// ---------------- launch ----------------
static float* sym_addr(const void* sym) {
    void* p = nullptr;
    cudaGetSymbolAddress(&p, sym);
    return (float*)p;
}

extern "C" void kernel_launch(void* const* d_in, const int* in_sizes, int n_in,
                              void* d_out, int out_size)
{
    (void)in_sizes; (void)n_in; (void)out_size;
    const float* x    = (const float*)d_in[0];
    const float* mask = (const float*)d_in[1];
    const float* Wq   = (const float*)d_in[2];
    const float* bq   = (const float*)d_in[3];
    const float* Wk   = (const float*)d_in[4];
    const float* bk   = (const float*)d_in[5];
    const float* Wv   = (const float*)d_in[6];
    const float* bv   = (const float*)d_in[7];
    const float* Wd   = (const float*)d_in[8];
    const float* bd   = (const float*)d_in[9];
    const float* lnw  = (const float*)d_in[10];
    const float* lnb  = (const float*)d_in[11];
    float* out = (float*)d_out;

    float* q    = sym_addr(g_q);
    float* k    = sym_addr(g_k);
    float* v    = sym_addr(g_v);
    float* ctx  = sym_addr(g_ctx);
    float* proj = sym_addr(g_proj);

    const int n4 = (MDIM * HDIM) / 4;
    const int qblocks = n4 / 256;

    reset_kernel<<<1, 32>>>();

    dim3 gg(32, 32);
    gemm_tf32_kernel<<<gg, 256>>>(x, Wq, bq, q, 0);
    gemm_tf32_kernel<<<gg, 256>>>(x, Wk, bk, k, 1);
    gemm_tf32_kernel<<<gg, 256>>>(x, Wv, bv, v, 2);

    quant_kernel<<<qblocks, 256>>>(q, n4, 0);
    quant_kernel<<<qblocks, 256>>>(k, n4, 1);
    quant_kernel<<<qblocks, 256>>>(v, n4, 2);

    scores_kernel<<<dim3(8, 8, 512), 256>>>();
    softmax_kernel<<<dim3(64, 512), 256>>>(mask);
    ctx_kernel<<<dim3(8, 512), 256>>>();

    quant_kernel<<<qblocks, 256>>>(ctx, n4, 5);

    gemm_tf32_kernel<<<gg, 256>>>(ctx, Wd, bd, proj, 6);

    ln_kernel<<<MDIM, 256>>>(x, lnw, lnb, out);
    quant_kernel<<<qblocks, 256>>>(out, n4, 7);
}

// round 7
// speedup vs baseline: 3.0654x; 1.1793x over previous
#include <cuda_runtime.h>
#include <cstdint>

// Problem shape (fixed)
#define BSZ   8
#define SSZ   512
#define HDIM  4096
#define NH    64
#define HD    64
#define MDIM  (BSZ*SSZ)      // 4096 rows
#define NHEADS (BSZ*NH)      // 512

// ---------------- scratch (device globals; no allocations allowed) ----------------
__device__ float g_q[(size_t)MDIM*HDIM];
__device__ float g_k[(size_t)MDIM*HDIM];
__device__ float g_v[(size_t)MDIM*HDIM];
__device__ float g_ctx[(size_t)MDIM*HDIM];
__device__ float g_proj[(size_t)MDIM*HDIM];
__device__ float g_sp[(size_t)NHEADS*SSZ*SSZ];   // scores, then probs (in-place)
__device__ float g_act[(size_t)MDIM*HDIM];       // tf32-rounded activations
__device__ float g_w[4][(size_t)HDIM*HDIM];      // tf32-rounded weights (q,k,v,d)
__device__ float g_maxes[8];
// 0=q 1=k 2=v 3=scores 4=probs 5=ctx 6=proj 7=final

// ---------------- helpers ----------------
__device__ __forceinline__ float scale_from_max(float m) {
    m = fmaxf(m, 1e-12f);
    return exp2f(15.0f - ceilf(log2f(m)));   // exact power of two
}
__device__ __forceinline__ float quantv(float x, float s, float inv) {
    float r = rintf(x * s);
    r = fminf(fmaxf(r, -32768.0f), 32767.0f);
    return r * inv;
}
__device__ __forceinline__ void atomic_amax(float* a, float v) {
    atomicMax((int*)a, __float_as_int(v));
}
__device__ __forceinline__ float block_reduce_max(float v, float* sm, int nthr) {
    int t = threadIdx.x;
    sm[t] = v; __syncthreads();
    for (int off = nthr >> 1; off > 0; off >>= 1) {
        if (t < off) sm[t] = fmaxf(sm[t], sm[t + off]);
        __syncthreads();
    }
    float r = sm[0]; __syncthreads();
    return r;
}
__device__ __forceinline__ float block_reduce_sum(float v, float* sm) {
    int t = threadIdx.x;
    sm[t] = v; __syncthreads();
    for (int off = blockDim.x >> 1; off > 0; off >>= 1) {
        if (t < off) sm[t] += sm[t + off];
        __syncthreads();
    }
    float r = sm[0]; __syncthreads();
    return r;
}
__device__ __forceinline__ float f2tf32f(float x) {
    uint32_t r;
    asm("cvt.rna.tf32.f32 %0, %1;" : "=r"(r) : "f"(x));
    return __uint_as_float(r);
}
__device__ __forceinline__ void mma_tf32(
    float& c0, float& c1, float& c2, float& c3,
    uint32_t a0, uint32_t a1, uint32_t a2, uint32_t a3,
    uint32_t b0, uint32_t b1)
{
    asm volatile(
        "mma.sync.aligned.m16n8k8.row.col.f32.tf32.tf32.f32 "
        "{%0,%1,%2,%3}, {%4,%5,%6,%7}, {%8,%9}, {%0,%1,%2,%3};"
        : "+f"(c0), "+f"(c1), "+f"(c2), "+f"(c3)
        : "r"(a0), "r"(a1), "r"(a2), "r"(a3), "r"(b0), "r"(b1));
}
__device__ __forceinline__ void cp_async16(uint32_t smem_addr, const void* gptr) {
    asm volatile("cp.async.cg.shared.global [%0], [%1], 16;" :: "r"(smem_addr), "l"(gptr));
}
__device__ __forceinline__ void cp_commit() {
    asm volatile("cp.async.commit_group;" ::: "memory");
}
template<int N> __device__ __forceinline__ void cp_wait() {
    asm volatile("cp.async.wait_group %0;" :: "n"(N) : "memory");
}
__device__ __forceinline__ uint32_t smem_u32(const void* p) {
    uint32_t a;
    asm("{ .reg .u64 t; cvta.to.shared.u64 t, %1; cvt.u32.u64 %0, t; }" : "=r"(a) : "l"(p));
    return a;
}
__device__ __forceinline__ uint32_t ldsf(const float* p) {
    return __float_as_uint(*p);
}

__global__ void reset_kernel() {
    if (threadIdx.x < 8) g_maxes[threadIdx.x] = 0.0f;
}

// ---------------- tf32 pre-round (fp32 -> tf32-rounded fp32) ----------------
__global__ void rnd_kernel(const float* __restrict__ src, float* __restrict__ dst, int n4) {
    int i = blockIdx.x * blockDim.x + threadIdx.x;
    if (i < n4) {
        float4 v = ((const float4*)src)[i];
        v.x = f2tf32f(v.x); v.y = f2tf32f(v.y); v.z = f2tf32f(v.z); v.w = f2tf32f(v.w);
        ((float4*)dst)[i] = v;
    }
}

// ---------------- quantize + tf32 round (in place; for MMA-consumed tensors) ----------------
__global__ void quant_rnd_kernel(float* __restrict__ p, int n4, int maxidx) {
    float s = scale_from_max(g_maxes[maxidx]);
    float inv = 1.0f / s;
    int i = blockIdx.x * blockDim.x + threadIdx.x;
    if (i < n4) {
        float4 v = ((float4*)p)[i];
        v.x = f2tf32f(quantv(v.x, s, inv));
        v.y = f2tf32f(quantv(v.y, s, inv));
        v.z = f2tf32f(quantv(v.z, s, inv));
        v.w = f2tf32f(quantv(v.w, s, inv));
        ((float4*)p)[i] = v;
    }
}

// ---------------- plain quantize (final output) ----------------
__global__ void quant_kernel(float* __restrict__ p, int n4, int maxidx) {
    float s = scale_from_max(g_maxes[maxidx]);
    float inv = 1.0f / s;
    int i = blockIdx.x * blockDim.x + threadIdx.x;
    if (i < n4) {
        float4 v = ((float4*)p)[i];
        v.x = quantv(v.x, s, inv);
        v.y = quantv(v.y, s, inv);
        v.z = quantv(v.z, s, inv);
        v.w = quantv(v.w, s, inv);
        ((float4*)p)[i] = v;
    }
}

// ---------------- tf32 tensor-core GEMM (pre-rounded inputs) ----------------
// C[m,n] = sum_k A[m,k]*W[n,k] + bias[n].  Block 128x128, BK=16, 8 warps, warp tile 64x32.
#define BKT 16
#define KSTRIDE 20

__global__ __launch_bounds__(256) void gemm_tf32_kernel(
    const float* __restrict__ A, const float* __restrict__ W,
    const float* __restrict__ bias, float* __restrict__ C, int maxidx)
{
    __shared__ float As[2][128][KSTRIDE];
    __shared__ float Bs[2][128][KSTRIDE];
    __shared__ float red[256];

    const int tid   = threadIdx.x;
    const int wid   = tid >> 5;
    const int lane  = tid & 31;
    const int g     = lane >> 2;
    const int tg    = lane & 3;
    const int warp_m = wid & 1;
    const int warp_n = wid >> 1;
    const int rowBase = blockIdx.y * 128;
    const int colBase = blockIdx.x * 128;

    const int c_row0 = tid >> 2;
    const int c_seg  = (tid & 3) << 2;
    const int c_row1 = c_row0 + 64;

    float acc[4][4][4];
#pragma unroll
    for (int mt = 0; mt < 4; mt++)
#pragma unroll
        for (int nt = 0; nt < 4; nt++)
#pragma unroll
            for (int i = 0; i < 4; i++) acc[mt][nt][i] = 0.0f;

    auto issue_copy = [&](int buf, int k0) {
        const float* asrc0 = A + (size_t)(rowBase + c_row0) * 4096 + k0 + c_seg;
        const float* asrc1 = A + (size_t)(rowBase + c_row1) * 4096 + k0 + c_seg;
        const float* bsrc0 = W + (size_t)(colBase + c_row0) * 4096 + k0 + c_seg;
        const float* bsrc1 = W + (size_t)(colBase + c_row1) * 4096 + k0 + c_seg;
        cp_async16((uint32_t)__cvta_generic_to_shared(&As[buf][c_row0][c_seg]), asrc0);
        cp_async16((uint32_t)__cvta_generic_to_shared(&As[buf][c_row1][c_seg]), asrc1);
        cp_async16((uint32_t)__cvta_generic_to_shared(&Bs[buf][c_row0][c_seg]), bsrc0);
        cp_async16((uint32_t)__cvta_generic_to_shared(&Bs[buf][c_row1][c_seg]), bsrc1);
        cp_commit();
    };

    issue_copy(0, 0);

    const int NITER = 4096 / BKT;
    for (int iter = 0; iter < NITER; iter++) {
        const int buf = iter & 1;
        if (iter + 1 < NITER) {
            issue_copy(buf ^ 1, (iter + 1) * BKT);
            cp_wait<1>();
        } else {
            cp_wait<0>();
        }
        __syncthreads();

#pragma unroll
        for (int ks = 0; ks < 2; ks++) {
            const int kb = ks * 8;
            uint32_t af[4][4];
#pragma unroll
            for (int mt = 0; mt < 4; mt++) {
                const int m = warp_m * 64 + mt * 16 + g;
                af[mt][0] = ldsf(&As[buf][m    ][kb + tg]);
                af[mt][1] = ldsf(&As[buf][m + 8][kb + tg]);
                af[mt][2] = ldsf(&As[buf][m    ][kb + tg + 4]);
                af[mt][3] = ldsf(&As[buf][m + 8][kb + tg + 4]);
            }
            uint32_t bf[4][2];
#pragma unroll
            for (int nt = 0; nt < 4; nt++) {
                const int n = warp_n * 32 + nt * 8 + g;
                bf[nt][0] = ldsf(&Bs[buf][n][kb + tg]);
                bf[nt][1] = ldsf(&Bs[buf][n][kb + tg + 4]);
            }
#pragma unroll
            for (int mt = 0; mt < 4; mt++)
#pragma unroll
                for (int nt = 0; nt < 4; nt++)
                    mma_tf32(acc[mt][nt][0], acc[mt][nt][1], acc[mt][nt][2], acc[mt][nt][3],
                             af[mt][0], af[mt][1], af[mt][2], af[mt][3],
                             bf[nt][0], bf[nt][1]);
        }
        __syncthreads();
    }

    float amax = 0.0f;
#pragma unroll
    for (int mt = 0; mt < 4; mt++) {
        const int row0 = rowBase + warp_m * 64 + mt * 16 + g;
#pragma unroll
        for (int nt = 0; nt < 4; nt++) {
            const int col = colBase + warp_n * 32 + nt * 8 + tg * 2;
            const float b0 = bias[col], b1 = bias[col + 1];
            float v0 = acc[mt][nt][0] + b0;
            float v1 = acc[mt][nt][1] + b1;
            float v2 = acc[mt][nt][2] + b0;
            float v3 = acc[mt][nt][3] + b1;
            *(float2*)(C + (size_t)row0 * 4096 + col)       = make_float2(v0, v1);
            *(float2*)(C + (size_t)(row0 + 8) * 4096 + col) = make_float2(v2, v3);
            amax = fmaxf(amax, fmaxf(fmaxf(fabsf(v0), fabsf(v1)), fmaxf(fabsf(v2), fabsf(v3))));
        }
    }
    amax = block_reduce_max(amax, red, 256);
    if (tid == 0) atomic_amax(&g_maxes[maxidx], amax);
}

// ---------------- scores = q @ k^T / 8 per head (tf32 mma) ----------------
// grid (4,4,512); block 256; tile 128x128, K=64 one-shot. Stride 68 => bank==lane.
#define SSTRIDE 68
#define SS_SMEM (2 * 128 * SSTRIDE * 4)

__global__ __launch_bounds__(256) void scores_mma_kernel() {
    extern __shared__ float sm[];
    float* Qs = sm;                      // [128][68]
    float* Ks = sm + 128 * SSTRIDE;      // [128][68]
    __shared__ float red[256];

    const int head = blockIdx.z;
    const int b = head >> 6, n = head & 63;
    const int i0 = blockIdx.x * 128, j0 = blockIdx.y * 128;
    const float* qb = g_q + (size_t)(b * 512 + i0) * 4096 + n * 64;
    const float* kb = g_k + (size_t)(b * 512 + j0) * 4096 + n * 64;

    const int tid  = threadIdx.x;
    const int wid  = tid >> 5;
    const int lane = tid & 31;
    const int g    = lane >> 2;
    const int tg   = lane & 3;
    const int warp_m = wid & 1;
    const int warp_n = wid >> 1;

    // load 128x64 q and k tiles via cp.async: 2048 16B-chunks each
#pragma unroll
    for (int it = 0; it < 8; it++) {
        int id = tid + it * 256;         // 0..2047
        int r  = id >> 4;                // 0..127
        int c  = (id & 15) << 2;         // 0..60
        cp_async16((uint32_t)__cvta_generic_to_shared(&Qs[r * SSTRIDE + c]),
                   qb + (size_t)r * 4096 + c);
        cp_async16((uint32_t)__cvta_generic_to_shared(&Ks[r * SSTRIDE + c]),
                   kb + (size_t)r * 4096 + c);
    }
    cp_commit();
    cp_wait<0>();
    __syncthreads();

    float acc[4][4][4];
#pragma unroll
    for (int mt = 0; mt < 4; mt++)
#pragma unroll
        for (int nt = 0; nt < 4; nt++)
#pragma unroll
            for (int i = 0; i < 4; i++) acc[mt][nt][i] = 0.0f;

#pragma unroll
    for (int ks = 0; ks < 8; ks++) {
        const int kbase = ks * 8;
        uint32_t af[4][4];
#pragma unroll
        for (int mt = 0; mt < 4; mt++) {
            const int m = warp_m * 64 + mt * 16 + g;
            af[mt][0] = ldsf(&Qs[(m    ) * SSTRIDE + kbase + tg]);
            af[mt][1] = ldsf(&Qs[(m + 8) * SSTRIDE + kbase + tg]);
            af[mt][2] = ldsf(&Qs[(m    ) * SSTRIDE + kbase + tg + 4]);
            af[mt][3] = ldsf(&Qs[(m + 8) * SSTRIDE + kbase + tg + 4]);
        }
        uint32_t bf[4][2];
#pragma unroll
        for (int nt = 0; nt < 4; nt++) {
            const int nn = warp_n * 32 + nt * 8 + g;
            bf[nt][0] = ldsf(&Ks[nn * SSTRIDE + kbase + tg]);
            bf[nt][1] = ldsf(&Ks[nn * SSTRIDE + kbase + tg + 4]);
        }
#pragma unroll
        for (int mt = 0; mt < 4; mt++)
#pragma unroll
            for (int nt = 0; nt < 4; nt++)
                mma_tf32(acc[mt][nt][0], acc[mt][nt][1], acc[mt][nt][2], acc[mt][nt][3],
                         af[mt][0], af[mt][1], af[mt][2], af[mt][3],
                         bf[nt][0], bf[nt][1]);
    }

    float amax = 0.0f;
    float* outb = g_sp + (size_t)head * 512 * 512;
#pragma unroll
    for (int mt = 0; mt < 4; mt++) {
        const int row0 = i0 + warp_m * 64 + mt * 16 + g;
#pragma unroll
        for (int nt = 0; nt < 4; nt++) {
            const int col = j0 + warp_n * 32 + nt * 8 + tg * 2;
            float v0 = acc[mt][nt][0] * 0.125f;
            float v1 = acc[mt][nt][1] * 0.125f;
            float v2 = acc[mt][nt][2] * 0.125f;
            float v3 = acc[mt][nt][3] * 0.125f;
            *(float2*)(outb + (size_t)row0 * 512 + col)       = make_float2(v0, v1);
            *(float2*)(outb + (size_t)(row0 + 8) * 512 + col) = make_float2(v2, v3);
            amax = fmaxf(amax, fmaxf(fmaxf(fabsf(v0), fabsf(v1)), fmaxf(fabsf(v2), fabsf(v3))));
        }
    }
    amax = block_reduce_max(amax, red, 256);
    if (tid == 0) atomic_amax(&g_maxes[3], amax);
}

// ---------------- softmax: quant scores + mask + softmax -> probs ----------------
__global__ __launch_bounds__(256) void softmax_kernel(const float* __restrict__ mask) {
    __shared__ float red8[8];
    const int head = blockIdx.y;
    const int b = head >> 6;
    const int warp = threadIdx.x >> 5, lane = threadIdx.x & 31;
    const int row = blockIdx.x * 8 + warp;
    float* sp = g_sp + ((size_t)head * 512 + row) * 512;
    const float* mrow = mask + (size_t)b * 512;

    const float s3 = scale_from_max(g_maxes[3]);
    const float inv3 = 1.0f / s3;

    float vals[16];
    float mx = -1e30f;
#pragma unroll
    for (int u = 0; u < 4; u++) {
        float4 v = ((const float4*)sp)[u * 32 + lane];
        float4 m = ((const float4*)mrow)[u * 32 + lane];
        vals[u * 4 + 0] = quantv(v.x, s3, inv3) + m.x;
        vals[u * 4 + 1] = quantv(v.y, s3, inv3) + m.y;
        vals[u * 4 + 2] = quantv(v.z, s3, inv3) + m.z;
        vals[u * 4 + 3] = quantv(v.w, s3, inv3) + m.w;
#pragma unroll
        for (int c = 0; c < 4; c++) mx = fmaxf(mx, vals[u * 4 + c]);
    }
#pragma unroll
    for (int off = 16; off > 0; off >>= 1)
        mx = fmaxf(mx, __shfl_xor_sync(0xffffffffu, mx, off));

    float sum = 0.0f;
#pragma unroll
    for (int u = 0; u < 16; u++) { vals[u] = expf(vals[u] - mx); sum += vals[u]; }
#pragma unroll
    for (int off = 16; off > 0; off >>= 1)
        sum += __shfl_xor_sync(0xffffffffu, sum, off);

    const float rs = 1.0f / sum;
    float amax = 0.0f;
#pragma unroll
    for (int u = 0; u < 4; u++) {
        float4 p;
        p.x = vals[u * 4 + 0] * rs;
        p.y = vals[u * 4 + 1] * rs;
        p.z = vals[u * 4 + 2] * rs;
        p.w = vals[u * 4 + 3] * rs;
        amax = fmaxf(amax, fmaxf(fmaxf(p.x, p.y), fmaxf(p.z, p.w)));
        ((float4*)sp)[u * 32 + lane] = p;
    }
#pragma unroll
    for (int off = 16; off > 0; off >>= 1)
        amax = fmaxf(amax, __shfl_xor_sync(0xffffffffu, amax, off));
    if (lane == 0) red8[warp] = amax;
    __syncthreads();
    if (threadIdx.x == 0) {
        float m = red8[0];
#pragma unroll
        for (int w = 1; w < 8; w++) m = fmaxf(m, red8[w]);
        atomic_amax(&g_maxes[4], m);
    }
}

// ---------------- ctx = quant(probs) @ v per head (tf32 mma) ----------------
// grid (4, 512); block 256; tile 128(i) x 64(d), K=512 streamed in 64-chunks.
// 8 warps: warp_m = wid&3 (4 x 32 rows), warp_n = wid>>2 (2 x 32 cols); warp tile 32x32.
#define CS_SMEM ((128 * SSTRIDE + 64 * SSTRIDE) * 4)

__global__ __launch_bounds__(256) void ctx_mma_kernel() {
    extern __shared__ float sm[];
    float* Ps = sm;                      // [128 i][68 j]
    float* Vs = sm + 128 * SSTRIDE;      // [64 d][68 j]
    __shared__ float red[256];

    const int head = blockIdx.y;
    const int b = head >> 6, n = head & 63;
    const int i0 = blockIdx.x * 128;
    const int tid  = threadIdx.x;
    const int wid  = tid >> 5;
    const int lane = tid & 31;
    const int g    = lane >> 2;
    const int tg   = lane & 3;
    const int warp_m = wid & 3;
    const int warp_n = wid >> 2;

    const float s4 = scale_from_max(g_maxes[4]);
    const float inv4 = 1.0f / s4;

    float acc[2][4][4];
#pragma unroll
    for (int mt = 0; mt < 2; mt++)
#pragma unroll
        for (int nt = 0; nt < 4; nt++)
#pragma unroll
            for (int i = 0; i < 4; i++) acc[mt][nt][i] = 0.0f;

    const float* pb = g_sp + ((size_t)head * 512 + i0) * 512;
    const float* vb = g_v + (size_t)(b * 512) * 4096 + n * 64;

    for (int j0 = 0; j0 < 512; j0 += 64) {
        // probs tile: 128 i x 64 j, quantize + tf32 round
#pragma unroll
        for (int it = 0; it < 8; it++) {
            int id = tid + it * 256;     // 0..2047
            int r  = id >> 4;            // i 0..127
            int c  = (id & 15) << 2;     // j 0..60
            float4 pv = *(const float4*)(pb + (size_t)r * 512 + j0 + c);
            Ps[r * SSTRIDE + c + 0] = f2tf32f(quantv(pv.x, s4, inv4));
            Ps[r * SSTRIDE + c + 1] = f2tf32f(quantv(pv.y, s4, inv4));
            Ps[r * SSTRIDE + c + 2] = f2tf32f(quantv(pv.z, s4, inv4));
            Ps[r * SSTRIDE + c + 3] = f2tf32f(quantv(pv.w, s4, inv4));
        }
        // v tile: 64 j x 64 d, store transposed Vs[d][j]
#pragma unroll
        for (int it = 0; it < 4; it++) {
            int id = tid + it * 256;     // 0..1023
            int r  = id >> 4;            // j 0..63
            int c  = (id & 15) << 2;     // d 0..60
            float4 vv = *(const float4*)(vb + (size_t)(j0 + r) * 4096 + c);
            Vs[(c + 0) * SSTRIDE + r] = vv.x;
            Vs[(c + 1) * SSTRIDE + r] = vv.y;
            Vs[(c + 2) * SSTRIDE + r] = vv.z;
            Vs[(c + 3) * SSTRIDE + r] = vv.w;
        }
        __syncthreads();

#pragma unroll
        for (int ks = 0; ks < 8; ks++) {
            const int kbase = ks * 8;
            uint32_t af[2][4];
#pragma unroll
            for (int mt = 0; mt < 2; mt++) {
                const int m = warp_m * 32 + mt * 16 + g;
                af[mt][0] = ldsf(&Ps[(m    ) * SSTRIDE + kbase + tg]);
                af[mt][1] = ldsf(&Ps[(m + 8) * SSTRIDE + kbase + tg]);
                af[mt][2] = ldsf(&Ps[(m    ) * SSTRIDE + kbase + tg + 4]);
                af[mt][3] = ldsf(&Ps[(m + 8) * SSTRIDE + kbase + tg + 4]);
            }
            uint32_t bf[4][2];
#pragma unroll
            for (int nt = 0; nt < 4; nt++) {
                const int nn = warp_n * 32 + nt * 8 + g;
                bf[nt][0] = ldsf(&Vs[nn * SSTRIDE + kbase + tg]);
                bf[nt][1] = ldsf(&Vs[nn * SSTRIDE + kbase + tg + 4]);
            }
#pragma unroll
            for (int mt = 0; mt < 2; mt++)
#pragma unroll
                for (int nt = 0; nt < 4; nt++)
                    mma_tf32(acc[mt][nt][0], acc[mt][nt][1], acc[mt][nt][2], acc[mt][nt][3],
                             af[mt][0], af[mt][1], af[mt][2], af[mt][3],
                             bf[nt][0], bf[nt][1]);
        }
        __syncthreads();
    }

    float amax = 0.0f;
#pragma unroll
    for (int mt = 0; mt < 2; mt++) {
        const int row0 = i0 + warp_m * 32 + mt * 16 + g;
#pragma unroll
        for (int nt = 0; nt < 4; nt++) {
            const int col = warp_n * 32 + nt * 8 + tg * 2;
            float* c0 = g_ctx + (size_t)(b * 512 + row0) * 4096 + n * 64 + col;
            float* c1 = g_ctx + (size_t)(b * 512 + row0 + 8) * 4096 + n * 64 + col;
            *(float2*)c0 = make_float2(acc[mt][nt][0], acc[mt][nt][1]);
            *(float2*)c1 = make_float2(acc[mt][nt][2], acc[mt][nt][3]);
            amax = fmaxf(amax, fmaxf(fmaxf(fabsf(acc[mt][nt][0]), fabsf(acc[mt][nt][1])),
                                     fmaxf(fabsf(acc[mt][nt][2]), fabsf(acc[mt][nt][3]))));
        }
    }
    amax = block_reduce_max(amax, red, 256);
    if (tid == 0) atomic_amax(&g_maxes[5], amax);
}

// ---------------- quant(proj) + residual + LayerNorm ----------------
__global__ __launch_bounds__(256) void ln_kernel(
    const float* __restrict__ x, const float* __restrict__ lnw,
    const float* __restrict__ lnb, float* __restrict__ out)
{
    __shared__ float ybuf[4096];
    __shared__ float red[256];
    const int r = blockIdx.x;
    const int tid = threadIdx.x;
    const float s6 = scale_from_max(g_maxes[6]);
    const float inv6 = 1.0f / s6;
    const float* xr = x + (size_t)r * 4096;
    const float* pr = g_proj + (size_t)r * 4096;

    float sum = 0.0f;
    for (int i = tid; i < 4096; i += 256) {
        float y = xr[i] + quantv(pr[i], s6, inv6);
        ybuf[i] = y;
        sum += y;
    }
    sum = block_reduce_sum(sum, red);
    const float mu = sum * (1.0f / 4096.0f);

    float s2 = 0.0f;
    for (int i = tid; i < 4096; i += 256) {
        float d = ybuf[i] - mu;
        s2 += d * d;
    }
    s2 = block_reduce_sum(s2, red);
    const float var = s2 * (1.0f / 4096.0f);
    const float rinv = rsqrtf(var + 1e-12f);

    float amax = 0.0f;
    float* orow = out + (size_t)r * 4096;
    for (int i = tid; i < 4096; i += 256) {
        float o = (ybuf[i] - mu) * rinv * lnw[i] + lnb[i];
        orow[i] = o;
        amax = fmaxf(amax, fabsf(o));
    }
    amax = block_reduce_max(amax, red, 256);
    if (tid == 0) atomic_amax(&g_maxes[7], amax);
}

// ---------------- launch ----------------
static void* sym_addr(const void* sym) {
    void* p = nullptr;
    cudaGetSymbolAddress(&p, sym);
    return p;
}

extern "C" void kernel_launch(void* const* d_in, const int* in_sizes, int n_in,
                              void* d_out, int out_size)
{
    (void)in_sizes; (void)n_in; (void)out_size;
    const float* x    = (const float*)d_in[0];
    const float* mask = (const float*)d_in[1];
    const float* Wq   = (const float*)d_in[2];
    const float* bq   = (const float*)d_in[3];
    const float* Wk   = (const float*)d_in[4];
    const float* bk   = (const float*)d_in[5];
    const float* Wv   = (const float*)d_in[6];
    const float* bv   = (const float*)d_in[7];
    const float* Wd   = (const float*)d_in[8];
    const float* bd   = (const float*)d_in[9];
    const float* lnw  = (const float*)d_in[10];
    const float* lnb  = (const float*)d_in[11];
    float* out = (float*)d_out;

    float* q    = (float*)sym_addr(g_q);
    float* k    = (float*)sym_addr(g_k);
    float* v    = (float*)sym_addr(g_v);
    float* ctx  = (float*)sym_addr(g_ctx);
    float* proj = (float*)sym_addr(g_proj);
    float* act  = (float*)sym_addr(g_act);
    float* w    = (float*)sym_addr(g_w);
    const size_t WSZ = (size_t)HDIM * HDIM;

    static int smem_set = 0;
    if (!smem_set) {
        cudaFuncSetAttribute(scores_mma_kernel,
                             cudaFuncAttributeMaxDynamicSharedMemorySize, SS_SMEM);
        cudaFuncSetAttribute(ctx_mma_kernel,
                             cudaFuncAttributeMaxDynamicSharedMemorySize, CS_SMEM);
        smem_set = 1;
    }

    const int n4 = (MDIM * HDIM) / 4;
    const int qblocks = n4 / 256;

    reset_kernel<<<1, 32>>>();

    // tf32 pre-round inputs
    rnd_kernel<<<qblocks, 256>>>(x,  act, n4);
    rnd_kernel<<<qblocks, 256>>>(Wq, w + 0 * WSZ, n4);
    rnd_kernel<<<qblocks, 256>>>(Wk, w + 1 * WSZ, n4);
    rnd_kernel<<<qblocks, 256>>>(Wv, w + 2 * WSZ, n4);
    rnd_kernel<<<qblocks, 256>>>(Wd, w + 3 * WSZ, n4);

    dim3 gg(32, 32);
    gemm_tf32_kernel<<<gg, 256>>>(act, w + 0 * WSZ, bq, q, 0);
    gemm_tf32_kernel<<<gg, 256>>>(act, w + 1 * WSZ, bk, k, 1);
    gemm_tf32_kernel<<<gg, 256>>>(act, w + 2 * WSZ, bv, v, 2);

    quant_rnd_kernel<<<qblocks, 256>>>(q, n4, 0);
    quant_rnd_kernel<<<qblocks, 256>>>(k, n4, 1);
    quant_rnd_kernel<<<qblocks, 256>>>(v, n4, 2);

    scores_mma_kernel<<<dim3(4, 4, 512), 256, SS_SMEM>>>();
    softmax_kernel<<<dim3(64, 512), 256>>>(mask);
    ctx_mma_kernel<<<dim3(4, 512), 256, CS_SMEM>>>();

    quant_rnd_kernel<<<qblocks, 256>>>(ctx, n4, 5);

    gemm_tf32_kernel<<<gg, 256>>>(ctx, w + 3 * WSZ, bd, proj, 6);

    ln_kernel<<<MDIM, 256>>>(x, lnw, lnb, out);
    quant_kernel<<<qblocks, 256>>>(out, n4, 7);
}